// round 16
// baseline (speedup 1.0000x reference)
#include <cuda_runtime.h>
#include <cuda_bf16.h>
#include <cuda_fp16.h>
#include <cstdint>
#include <cstddef>

// ---------------------------------------------------------------------------
// GraphSAGE 3-layer forward, fp32 I/O, GB300 (sm_103a host, compute_103 PTX).
//   * transform-then-aggregate (aggregation is linear)
//   * GEMM: warp mma.sync bf16 hi/lo split (fragment reuse), persistent CTAs,
//     B resident, dual 8-warp groups with private pipelines (named barriers).
//   * Y stored fp16 (halves edge-gather traffic); fp32 accumulation.
//   * SM-PARTITIONED OVERLAP: gemm0 uses 128 SMs; the CSR-build chain runs on
//     a side stream with capped grid-stride kernels in the ~20 free SMs
//     (R15 fork failed because full-GPU gemm left no SM for the side chain).
// ---------------------------------------------------------------------------

#define NMAX 100000
#define EMAX 1600000

__device__ float  g_SA[(size_t)NMAX * 128];
__device__ float  g_SB[(size_t)NMAX * 128];
__device__ __half g_Yh[(size_t)NMAX * 128];
__device__ float  g_inv[NMAX];
__device__ int    g_deg[NMAX];
__device__ int    g_off[NMAX];
__device__ int    g_cur[NMAX];
__device__ int    g_csr[EMAX];
__device__ int    g_bsum[1024];
__device__ __nv_bfloat16 g_B0[2 * 256 * 128];
__device__ __nv_bfloat16 g_B1[2 * 256 * 128];
__device__ __nv_bfloat16 g_B2[2 * 128 * 128];
__device__ float g_b0p[128];
__device__ float g_b1p[128];
__device__ float g_b2p[64];

// ---------------------------------------------------------------------------
// PTX helpers
// ---------------------------------------------------------------------------
__device__ __forceinline__ uint32_t smem_u32(const void* p) {
    uint32_t a;
    asm("{ .reg .u64 t; cvta.to.shared.u64 t, %1; cvt.u32.u64 %0, t; }"
        : "=r"(a) : "l"(p));
    return a;
}

__device__ __forceinline__ void ldsm4(uint32_t* r, uint32_t addr) {
    asm volatile("ldmatrix.sync.aligned.m8n8.x4.shared.b16 {%0,%1,%2,%3}, [%4];"
        : "=r"(r[0]), "=r"(r[1]), "=r"(r[2]), "=r"(r[3]) : "r"(addr));
}

__device__ __forceinline__ void mma16816(float* c, const uint32_t* a, const uint32_t* b) {
    asm volatile(
        "mma.sync.aligned.m16n8k16.row.col.f32.bf16.bf16.f32 "
        "{%0,%1,%2,%3}, {%4,%5,%6,%7}, {%8,%9}, {%0,%1,%2,%3};"
        : "+f"(c[0]), "+f"(c[1]), "+f"(c[2]), "+f"(c[3])
        : "r"(a[0]), "r"(a[1]), "r"(a[2]), "r"(a[3]), "r"(b[0]), "r"(b[1]));
}

__device__ __forceinline__ void cpasync16(uint32_t dst, const void* src) {
    asm volatile("cp.async.cg.shared.global [%0], [%1], 16;"
                 :: "r"(dst), "l"(src) : "memory");
}
__device__ __forceinline__ void cpasync_commit() {
    asm volatile("cp.async.commit_group;" ::: "memory");
}
__device__ __forceinline__ void cpasync_wait0() {
    asm volatile("cp.async.wait_group 0;" ::: "memory");
}
__device__ __forceinline__ void bar_named(int id, int cnt) {
    asm volatile("bar.sync %0, %1;" :: "r"(id), "r"(cnt) : "memory");
}

__device__ __forceinline__ float2 h2f2(uint32_t u) {
    __half2 h = *reinterpret_cast<__half2*>(&u);
    return __half22float2(h);
}

// ---------------------------------------------------------------------------
// graph-structure kernels (side stream; capped grids so they fit the SM
// partition left free by gemm0)
// ---------------------------------------------------------------------------
__global__ void deg_zero_kernel(int* __restrict__ deg, int n) {
    int i = blockIdx.x * blockDim.x + threadIdx.x;
    if (i < n) deg[i] = 0;
}

__global__ void deg_count_kernel(int* __restrict__ deg, const int* __restrict__ dst, int e) {
    int stride = gridDim.x * blockDim.x;
    for (int i = blockIdx.x * blockDim.x + threadIdx.x; i < e; i += stride)
        atomicAdd(&deg[dst[i]], 1);
}

__global__ __launch_bounds__(1024) void scan1_kernel(
    const int* __restrict__ deg, int* __restrict__ off, int* __restrict__ bsum, int n)
{
    __shared__ int sh[1024];
    int t = threadIdx.x;
    int i = blockIdx.x * 1024 + t;
    int v = (i < n) ? deg[i] : 0;
    sh[t] = v;
    __syncthreads();
    #pragma unroll
    for (int s = 1; s < 1024; s <<= 1) {
        int x = (t >= s) ? sh[t - s] : 0;
        __syncthreads();
        sh[t] += x;
        __syncthreads();
    }
    if (i < n) off[i] = sh[t] - v;
    if (t == 1023) bsum[blockIdx.x] = sh[t];
}

// finalize offsets (local scan of bsum), copy to cur, compute inv-degree
__global__ __launch_bounds__(256) void scan3_inv_kernel(
    int* __restrict__ off, int* __restrict__ cur,
    const int* __restrict__ bsum, const int* __restrict__ deg,
    float* __restrict__ inv, int n, int nb)
{
    __shared__ int sh[128];                  // nb <= 98
    int t = threadIdx.x;
    if (t < 128) sh[t] = (t < nb) ? bsum[t] : 0;
    __syncthreads();
    #pragma unroll
    for (int s = 1; s < 128; s <<= 1) {
        int x = (t >= s && t < 128) ? sh[t - s] : 0;
        __syncthreads();
        if (t < 128) sh[t] += x;             // inclusive scan
        __syncthreads();
    }
    for (int i = blockIdx.x * blockDim.x + t; i < n; i += gridDim.x * blockDim.x) {
        int b = i >> 10;
        int pre = (b == 0) ? 0 : sh[b - 1];
        int o = off[i] + pre;
        off[i] = o;
        cur[i] = o;
        int d = deg[i];
        inv[i] = 1.0f / (float)(d > 1 ? d : 1);
    }
}

__global__ void csr_fill_kernel(const int* __restrict__ src, const int* __restrict__ dst,
                                int* __restrict__ cur, int* __restrict__ csr, int e) {
    int stride = gridDim.x * blockDim.x;
    for (int i = blockIdx.x * blockDim.x + threadIdx.x; i < e; i += stride) {
        int d = dst[i];
        int p = atomicAdd(&cur[d], 1);
        csr[p] = src[i];
    }
}

// ---------------------------------------------------------------------------
// weight prepack
// ---------------------------------------------------------------------------
__device__ __forceinline__ void pack_one(__nv_bfloat16* img, int NB, int nrow, int k, float w) {
    __nv_bfloat16 h = __float2bfloat16(w);
    __nv_bfloat16 l = __float2bfloat16(w - __bfloat162float(h));
    uint32_t off = (uint32_t)nrow * 256u
                 + ((((uint32_t)k >> 3) ^ ((uint32_t)nrow & 7u)) << 4)
                 + ((uint32_t)k & 7u) * 2u;
    char* hi = reinterpret_cast<char*>(img);
    char* lo = reinterpret_cast<char*>(img + (size_t)NB * 128);
    *reinterpret_cast<__nv_bfloat16*>(hi + off) = h;
    *reinterpret_cast<__nv_bfloat16*>(lo + off) = l;
}

__global__ void pack_all_kernel(
    const float* __restrict__ ws0, const float* __restrict__ wn0, const float* __restrict__ b0,
    const float* __restrict__ ws1, const float* __restrict__ wn1, const float* __restrict__ b1,
    const float* __restrict__ ws2, const float* __restrict__ wn2, const float* __restrict__ b2,
    __nv_bfloat16* __restrict__ B0, __nv_bfloat16* __restrict__ B1, __nv_bfloat16* __restrict__ B2,
    float* __restrict__ b0p, float* __restrict__ b1p, float* __restrict__ b2p)
{
    int idx = blockIdx.x * blockDim.x + threadIdx.x;
    if (idx < 32768) {
        int nrow = idx >> 7, k = idx & 127;
        float w = (nrow < 128) ? ws0[k * 128 + nrow] : wn0[k * 128 + (nrow - 128)];
        pack_one(B0, 256, nrow, k, w);
    } else if (idx < 65536) {
        int t = idx - 32768;
        int nrow = t >> 7, k = t & 127;
        float w = (nrow < 128) ? ws1[k * 128 + nrow] : wn1[k * 128 + (nrow - 128)];
        pack_one(B1, 256, nrow, k, w);
    } else if (idx < 65536 + 16384) {
        int t = idx - 65536;
        int nrow = t >> 7, k = t & 127;
        float w = 0.0f;
        if (nrow < 64) { if (nrow < 47) w = ws2[k * 47 + nrow]; }
        else           { int jj = nrow - 64; if (jj < 47) w = wn2[k * 47 + jj]; }
        pack_one(B2, 128, nrow, k, w);
    }
    if (idx < 128) { b0p[idx] = b0[idx]; b1p[idx] = b1[idx]; }
    if (idx < 64)  { b2p[idx] = (idx < 47) ? b2[idx] : 0.0f; }
}

// ---------------------------------------------------------------------------
// PERSISTENT HMMA GEMM — dual 8-warp groups, private 32-row tile pipelines
// (cp.async double-buffered stage + Ah/Al), own named barrier per group;
// B + bias shared (resident). Fragment-reuse mma loop (3 combos per k-step).
// Outputs: S (fp32, +bias, stride RS), Y (fp16, stride RS).
// ---------------------------------------------------------------------------
template<int NB, int RS, bool RELU>
__global__ void __launch_bounds__(512, 1) gemm_mma_kernel(
    const float* __restrict__ A, int n, int ntiles,
    const __nv_bfloat16* __restrict__ Bimg, const float* __restrict__ bias,
    float* __restrict__ S, __half* __restrict__ Y)
{
    constexpr int WN  = NB / 8;
    constexpr int NBT = (WN / 16 > 0) ? WN / 16 : 1;
    constexpr int NT  = WN / 8;
    constexpr int HC  = NB / 2;
    constexpr int BREG = 2 * NB * 256;

    extern __shared__ char smem[];
    float* sBias = reinterpret_cast<float*>(smem + BREG);

    const int tid    = threadIdx.x;
    const int g      = tid >> 8;
    const int ltid   = tid & 255;
    const int wgrp   = ltid >> 5;
    const int lane   = tid & 31;

    {
        const uint4* srcp = reinterpret_cast<const uint4*>(Bimg);
        uint4* dstp = reinterpret_cast<uint4*>(smem);
        constexpr int CNT = BREG / 16;
        #pragma unroll
        for (int i = 0; i < CNT / 512; i++)
            dstp[tid + i * 512] = srcp[tid + i * 512];
        if (tid < HC) sBias[tid] = bias[tid];
    }

    const uint32_t sb   = smem_u32(smem);
    const int GB        = BREG + 512 + g * 49152;
    const uint32_t aAh  = sb + GB + 32768;
    const uint32_t aAl  = sb + GB + 40960;
    const uint32_t aBh  = sb;
    const uint32_t aBl  = sb + NB * 256;

    const int arow = ltid >> 3;
    const int acol = (ltid & 7) * 16;

    auto loadA_async = [&](int t, int buf) {
        int gr = t * 32 + arow;
        if (gr > n - 1) gr = n - 1;
        const float* src = A + (size_t)gr * 128 + acol;
        uint32_t dst = sb + GB + buf * 16384 + arow * 512 + acol * 4;
        #pragma unroll
        for (int j = 0; j < 4; j++)
            cpasync16(dst + j * 16, src + j * 4);
        cpasync_commit();
    };

    auto convert = [&](int buf) {
        const float4* sp = reinterpret_cast<const float4*>(
            smem + GB + buf * 16384 + arow * 512 + acol * 4);
        float4 f0 = sp[0], f1 = sp[1], f2 = sp[2], f3 = sp[3];
        float v[16] = {f0.x, f0.y, f0.z, f0.w, f1.x, f1.y, f1.z, f1.w,
                       f2.x, f2.y, f2.z, f2.w, f3.x, f3.y, f3.z, f3.w};
        #pragma unroll
        for (int h = 0; h < 2; h++) {
            struct alignas(16) BF8 { __nv_bfloat16 b[8]; } hh, ll;
            #pragma unroll
            for (int q = 0; q < 8; q++) {
                float x = v[h * 8 + q];
                if (RELU) x = fmaxf(x, 0.0f);
                __nv_bfloat16 hb = __float2bfloat16(x);
                hh.b[q] = hb;
                ll.b[q] = __float2bfloat16(x - __bfloat162float(hb));
            }
            int c16 = (ltid & 7) * 2 + h;
            uint32_t o = (uint32_t)arow * 256u
                       + (uint32_t)((c16 ^ (arow & 7)) << 4);
            *reinterpret_cast<BF8*>(smem + GB + 32768 + o) = hh;
            *reinterpret_cast<BF8*>(smem + GB + 40960 + o) = ll;
        }
    };

    int rA[2], swA[2];
    #pragma unroll
    for (int mt = 0; mt < 2; mt++) {
        int row = mt * 16 + (lane & 15);
        rA[mt]  = row * 256;
        swA[mt] = row & 7;
    }
    const int hiA = lane >> 4;
    int rB[NBT], swB[NBT];
    #pragma unroll
    for (int bt = 0; bt < NBT; bt++) {
        int row = wgrp * WN + bt * 16 + ((lane >> 4) << 3) + (lane & 7);
        rB[bt]  = row * 256;
        swB[bt] = row & 7;
    }
    const int hB = (lane >> 3) & 1;

    __syncthreads();

    const int barid = g + 1;
    const int tstride = 2 * gridDim.x;
    int t0 = blockIdx.x * 2 + g;

    int buf = 0;
    if (t0 < ntiles) loadA_async(t0, 0);

    for (int t = t0; t < ntiles; t += tstride) {
        cpasync_wait0();
        convert(buf);
        int tn = t + tstride;
        if (tn < ntiles) loadA_async(tn, buf ^ 1);
        bar_named(barid, 256);

        float acc[2][NT][4];
        #pragma unroll
        for (int mt = 0; mt < 2; mt++)
            #pragma unroll
            for (int nt = 0; nt < NT; nt++)
                #pragma unroll
                for (int q = 0; q < 4; q++)
                    acc[mt][nt][q] = 0.0f;

        #pragma unroll
        for (int s = 0; s < 8; s++) {
            uint32_t ah[2][4], al[2][4];
            #pragma unroll
            for (int mt = 0; mt < 2; mt++) {
                uint32_t ofsA = (uint32_t)(((2 * s + hiA) ^ swA[mt]) << 4);
                ldsm4(ah[mt], aAh + rA[mt] + ofsA);
                ldsm4(al[mt], aAl + rA[mt] + ofsA);
            }
            uint32_t bh[NBT][4], bl[NBT][4];
            #pragma unroll
            for (int bt = 0; bt < NBT; bt++) {
                uint32_t ofsB = (uint32_t)(((2 * s + hB) ^ swB[bt]) << 4);
                ldsm4(bh[bt], aBh + rB[bt] + ofsB);
                ldsm4(bl[bt], aBl + rB[bt] + ofsB);
            }
            #pragma unroll
            for (int mt = 0; mt < 2; mt++)
                #pragma unroll
                for (int nt = 0; nt < NT; nt++) {
                    const uint32_t* bhp = &bh[nt >> 1][(nt & 1) * 2];
                    const uint32_t* blp = &bl[nt >> 1][(nt & 1) * 2];
                    mma16816(acc[mt][nt], ah[mt], bhp);
                    mma16816(acc[mt][nt], al[mt], bhp);
                    mma16816(acc[mt][nt], ah[mt], blp);
                }
        }
        bar_named(barid, 256);

        int m0 = t * 32;
        #pragma unroll
        for (int mt = 0; mt < 2; mt++) {
            int gr0 = m0 + mt * 16 + (lane >> 2);
            #pragma unroll
            for (int nt = 0; nt < NT; nt++) {
                int J = wgrp * WN + nt * 8 + (lane & 3) * 2;
                #pragma unroll
                for (int rr = 0; rr < 2; rr++) {
                    int gr = gr0 + rr * 8;
                    if (gr >= n) continue;
                    float c0 = acc[mt][nt][rr * 2 + 0];
                    float c1 = acc[mt][nt][rr * 2 + 1];
                    if (J < HC) {
                        if (J < RS) {
                            float2 o = make_float2(c0 + sBias[J], c1 + sBias[J + 1]);
                            *reinterpret_cast<float2*>(S + (size_t)gr * RS + J) = o;
                        }
                    } else {
                        int j2 = J - HC;
                        if (j2 < RS) {
                            __half2 o = __floats2half2_rn(c0, c1);
                            *reinterpret_cast<__half2*>(Y + (size_t)gr * RS + j2) = o;
                        }
                    }
                }
            }
        }
        buf ^= 1;
    }
}

// ---------------------------------------------------------------------------
// Mid-layer gather aggregation (fp16 Y, 128 cols): one warp per node,
// 8 edges in flight.  S[node] += inv[node] * sum_{in-edges} Y[src]
// ---------------------------------------------------------------------------
__global__ __launch_bounds__(256) void agg_mid_kernel(
    const __half* __restrict__ Yh, float* __restrict__ S,
    const int* __restrict__ csr, const int* __restrict__ off,
    const int* __restrict__ deg, const float* __restrict__ inv, int n)
{
    int w    = (blockIdx.x * blockDim.x + threadIdx.x) >> 5;
    int lane = threadIdx.x & 31;
    if (w >= n) return;

    int base = off[w];
    int dg   = deg[w];
    if (dg == 0) return;

    const uint2* Yb = reinterpret_cast<const uint2*>(Yh);

    float4 a0 = make_float4(0.f, 0.f, 0.f, 0.f);
    float4 a1 = a0;

    int i = 0;
    for (; i + 7 < dg; i += 8) {
        uint2 v[8];
        #pragma unroll
        for (int k = 0; k < 8; k++) {
            int s = __ldg(&csr[base + i + k]);
            v[k] = __ldg(Yb + (size_t)s * 32 + lane);
        }
        #pragma unroll
        for (int k = 0; k < 8; k += 2) {
            float2 p0 = h2f2(v[k].x),     p1 = h2f2(v[k].y);
            float2 q0 = h2f2(v[k + 1].x), q1 = h2f2(v[k + 1].y);
            a0.x += p0.x; a0.y += p0.y; a0.z += p1.x; a0.w += p1.y;
            a1.x += q0.x; a1.y += q0.y; a1.z += q1.x; a1.w += q1.y;
        }
    }
    for (; i < dg; i++) {
        int s = __ldg(&csr[base + i]);
        uint2 v = __ldg(Yb + (size_t)s * 32 + lane);
        float2 p0 = h2f2(v.x), p1 = h2f2(v.y);
        a0.x += p0.x; a0.y += p0.y; a0.z += p1.x; a0.w += p1.y;
    }

    float iv = __ldg(&inv[w]);
    float4 cur = *reinterpret_cast<const float4*>(S + (size_t)w * 128 + lane * 4);
    cur.x += iv * (a0.x + a1.x);
    cur.y += iv * (a0.y + a1.y);
    cur.z += iv * (a0.z + a1.z);
    cur.w += iv * (a0.w + a1.w);
    *reinterpret_cast<float4*>(S + (size_t)w * 128 + lane * 4) = cur;
}

// ---------------------------------------------------------------------------
// Final aggregation (layer 2, stride 48, 47-col output): TWO nodes per warp.
// ---------------------------------------------------------------------------
__global__ __launch_bounds__(256) void agg_out2_kernel(
    const __half* __restrict__ Yh, const float* __restrict__ S,
    const int* __restrict__ csr, const int* __restrict__ off,
    const int* __restrict__ deg, const float* __restrict__ inv, int n,
    float* __restrict__ out)
{
    int warp = (blockIdx.x * blockDim.x + threadIdx.x) >> 5;
    int lane = threadIdx.x & 31;
    int sub  = lane >> 4;
    int l    = lane & 15;
    int w    = warp * 2 + sub;
    if (w >= n) return;
    if (l >= 12) return;

    int base = off[w];
    int dg   = deg[w];

    const uint2* Yb = reinterpret_cast<const uint2*>(Yh);

    float4 a0 = make_float4(0.f, 0.f, 0.f, 0.f);
    float4 a1 = a0;

    int i = 0;
    for (; i + 7 < dg; i += 8) {
        uint2 v[8];
        #pragma unroll
        for (int k = 0; k < 8; k++) {
            int s = __ldg(&csr[base + i + k]);
            v[k] = __ldg(Yb + (size_t)s * 12 + l);
        }
        #pragma unroll
        for (int k = 0; k < 8; k += 2) {
            float2 p0 = h2f2(v[k].x),     p1 = h2f2(v[k].y);
            float2 q0 = h2f2(v[k + 1].x), q1 = h2f2(v[k + 1].y);
            a0.x += p0.x; a0.y += p0.y; a0.z += p1.x; a0.w += p1.y;
            a1.x += q0.x; a1.y += q0.y; a1.z += q1.x; a1.w += q1.y;
        }
    }
    for (; i < dg; i++) {
        int s = __ldg(&csr[base + i]);
        uint2 v = __ldg(Yb + (size_t)s * 12 + l);
        float2 p0 = h2f2(v.x), p1 = h2f2(v.y);
        a0.x += p0.x; a0.y += p0.y; a0.z += p1.x; a0.w += p1.y;
    }

    float iv = __ldg(&inv[w]);
    float4 cur = *reinterpret_cast<const float4*>(S + (size_t)w * 48 + l * 4);
    cur.x += iv * (a0.x + a1.x);
    cur.y += iv * (a0.y + a1.y);
    cur.z += iv * (a0.z + a1.z);
    cur.w += iv * (a0.w + a1.w);

    int col = l * 4;
    float vals[4] = {cur.x, cur.y, cur.z, cur.w};
    #pragma unroll
    for (int c = 0; c < 4; c++)
        if (col + c < 47) out[(size_t)w * 47 + col + c] = vals[c];
}

// ---------------------------------------------------------------------------
extern "C" void kernel_launch(void* const* d_in, const int* in_sizes, int n_in,
                              void* d_out, int out_size)
{
    const float* x   = (const float*)d_in[0];
    const int*   src = (const int*)d_in[1];
    const int*   dst = (const int*)d_in[2];
    const float* ws0 = (const float*)d_in[3];
    const float* wn0 = (const float*)d_in[4];
    const float* b0  = (const float*)d_in[5];
    const float* ws1 = (const float*)d_in[6];
    const float* wn1 = (const float*)d_in[7];
    const float* b1  = (const float*)d_in[8];
    const float* ws2 = (const float*)d_in[9];
    const float* wn2 = (const float*)d_in[10];
    const float* b2  = (const float*)d_in[11];
    float* out = (float*)d_out;

    const int n = in_sizes[0] / 128;   // 100000
    const int e = in_sizes[1];         // 1600000

    float *SA, *SB, *inv, *b0p, *b1p, *b2p;
    __half* Yh;
    __nv_bfloat16 *B0, *B1, *B2;
    int *deg, *off, *cur, *csr, *bsum;
    cudaGetSymbolAddress((void**)&SA,   g_SA);
    cudaGetSymbolAddress((void**)&SB,   g_SB);
    cudaGetSymbolAddress((void**)&Yh,   g_Yh);
    cudaGetSymbolAddress((void**)&inv,  g_inv);
    cudaGetSymbolAddress((void**)&deg,  g_deg);
    cudaGetSymbolAddress((void**)&off,  g_off);
    cudaGetSymbolAddress((void**)&cur,  g_cur);
    cudaGetSymbolAddress((void**)&csr,  g_csr);
    cudaGetSymbolAddress((void**)&bsum, g_bsum);
    cudaGetSymbolAddress((void**)&B0,   g_B0);
    cudaGetSymbolAddress((void**)&B1,   g_B1);
    cudaGetSymbolAddress((void**)&B2,   g_B2);
    cudaGetSymbolAddress((void**)&b0p,  g_b0p);
    cudaGetSymbolAddress((void**)&b1p,  g_b1p);
    cudaGetSymbolAddress((void**)&b2p,  g_b2p);

    const int SMEM_BIG   = 2 * 256 * 256 + 512 + 2 * 49152;   // 229888
    const int SMEM_SMALL = 2 * 128 * 256 + 512 + 2 * 49152;   // 164352
    cudaFuncSetAttribute(gemm_mma_kernel<256, 128, false>,
                         cudaFuncAttributeMaxDynamicSharedMemorySize, SMEM_BIG);
    cudaFuncSetAttribute(gemm_mma_kernel<256, 128, true>,
                         cudaFuncAttributeMaxDynamicSharedMemorySize, SMEM_BIG);
    cudaFuncSetAttribute(gemm_mma_kernel<128, 48, true>,
                         cudaFuncAttributeMaxDynamicSharedMemorySize, SMEM_SMALL);

    const int ntiles   = (n + 31) / 32;     // 3125
    const int PGRID0   = 128;               // gemm0: leave ~20 SMs for CSR chain
    const int PGRID    = 148;               // gemm1/2: full machine
    const int ablocks  = (n * 32 + 255) / 256;
    const int aoblocks = (((n + 1) / 2) * 32 + 255) / 256;
    const int nb       = (n + 1023) / 1024; // 98
    const int SIDEB    = 48;                // capped side-chain grids

    // Fork side stream for the CSR-build chain (independent of pack now).
    cudaStream_t s2;
    cudaStreamCreateWithFlags(&s2, cudaStreamNonBlocking);
    cudaEvent_t evF, evJ;
    cudaEventCreateWithFlags(&evF, cudaEventDisableTiming);
    cudaEventCreateWithFlags(&evJ, cudaEventDisableTiming);

    cudaEventRecord(evF, 0);
    cudaStreamWaitEvent(s2, evF, 0);

    // side stream: full structure chain, SM-bounded grids
    deg_zero_kernel<<<(n + 255) / 256, 256, 0, s2>>>(deg, n);
    deg_count_kernel<<<SIDEB, 256, 0, s2>>>(deg, dst, e);
    scan1_kernel<<<nb, 1024, 0, s2>>>(deg, off, bsum, n);
    scan3_inv_kernel<<<SIDEB, 256, 0, s2>>>(off, cur, bsum, deg, inv, n, nb);
    csr_fill_kernel<<<SIDEB, 256, 0, s2>>>(src, dst, cur, csr, e);
    cudaEventRecord(evJ, s2);

    // main stream: pack -> gemm0 (128 SMs; overlaps side chain)
    pack_all_kernel<<<(81920 + 255) / 256, 256>>>(
        ws0, wn0, b0, ws1, wn1, b1, ws2, wn2, b2,
        B0, B1, B2, b0p, b1p, b2p);

    gemm_mma_kernel<256, 128, false><<<PGRID0, 512, SMEM_BIG>>>(
        x, n, ntiles, B0, b0p, SA, Yh);

    cudaStreamWaitEvent(0, evJ, 0);                                   // join

    agg_mid_kernel<<<ablocks, 256>>>(Yh, SA, csr, off, deg, inv, n);

    gemm_mma_kernel<256, 128, true><<<PGRID, 512, SMEM_BIG>>>(
        SA, n, ntiles, B1, b1p, SB, Yh);
    agg_mid_kernel<<<ablocks, 256>>>(Yh, SB, csr, off, deg, inv, n);

    gemm_mma_kernel<128, 48, true><<<PGRID, 512, SMEM_SMALL>>>(
        SB, n, ntiles, B2, b2p, SA, Yh);

    agg_out2_kernel<<<aoblocks, 256>>>(Yh, SA, csr, off, deg, inv, n, out);
}